// round 3
// baseline (speedup 1.0000x reference)
#include <cuda_runtime.h>
#include <cstddef>

#define WIN 7
#define NTOK 49
#define NH 16
#define HD 32
#define CDIM 512
#define BATCH 2048
#define M_TOT (BATCH * NTOK)   // 100352 = 784 * 128

// ---------------- scratch (static device globals; no allocations) ----------------
__device__ float g_qkv[(size_t)M_TOT * 3 * CDIM];   // 616 MB
__device__ float g_buf1[(size_t)M_TOT * CDIM];      // 205 MB (attention out)
__device__ float g_buf2[(size_t)M_TOT * CDIM];      // 205 MB (gamma out)

// ---------------- SGEMM: C[M,N] = A[M,K] * B[N,K]^T + bias[N] ----------------
// A row-major MxK, B row-major NxK (both K-contiguous -> NT layout).
// BM=BN=128, BK=8, 256 threads, 8x8 per-thread micro-tile.
// Requires: M % 128 == 0, N % 128 == 0, K % 8 == 0, K*4 bytes 16B-aligned rows.
__global__ __launch_bounds__(256, 2)
void sgemm_nt_bias(const float* __restrict__ A, const float* __restrict__ B,
                   const float* __restrict__ bias, float* __restrict__ C,
                   int M, int N, int K)
{
    __shared__ float As[8][128];
    __shared__ float Bs[8][128];

    const int bx = blockIdx.x;   // N tile
    const int by = blockIdx.y;   // M tile
    const int tid = threadIdx.x;
    const int tx = tid & 15;     // 0..15 -> N micro
    const int ty = tid >> 4;     // 0..15 -> M micro

    const float* Ag = A + (size_t)by * 128 * K;
    const float* Bg = B + (size_t)bx * 128 * K;

    // loader mapping: 256 threads cover 128 rows x 8 cols (one float4 each)
    const int lrow = tid >> 1;          // 0..127
    const int lcol = (tid & 1) * 4;     // 0 or 4

    float acc[8][8];
#pragma unroll
    for (int i = 0; i < 8; i++)
#pragma unroll
        for (int j = 0; j < 8; j++) acc[i][j] = 0.f;

    for (int k0 = 0; k0 < K; k0 += 8) {
        float4 a4 = *(const float4*)(Ag + (size_t)lrow * K + k0 + lcol);
        float4 b4 = *(const float4*)(Bg + (size_t)lrow * K + k0 + lcol);
        As[lcol + 0][lrow] = a4.x; As[lcol + 1][lrow] = a4.y;
        As[lcol + 2][lrow] = a4.z; As[lcol + 3][lrow] = a4.w;
        Bs[lcol + 0][lrow] = b4.x; Bs[lcol + 1][lrow] = b4.y;
        Bs[lcol + 2][lrow] = b4.z; Bs[lcol + 3][lrow] = b4.w;
        __syncthreads();

#pragma unroll
        for (int kk = 0; kk < 8; kk++) {
            float4 a0 = *(const float4*)&As[kk][ty * 8];
            float4 a1 = *(const float4*)&As[kk][ty * 8 + 4];
            float4 b0 = *(const float4*)&Bs[kk][tx * 8];
            float4 b1 = *(const float4*)&Bs[kk][tx * 8 + 4];
            float ar[8] = {a0.x, a0.y, a0.z, a0.w, a1.x, a1.y, a1.z, a1.w};
            float br[8] = {b0.x, b0.y, b0.z, b0.w, b1.x, b1.y, b1.z, b1.w};
#pragma unroll
            for (int i = 0; i < 8; i++)
#pragma unroll
                for (int j = 0; j < 8; j++)
                    acc[i][j] = fmaf(ar[i], br[j], acc[i][j]);
        }
        __syncthreads();
    }

#pragma unroll
    for (int i = 0; i < 8; i++) {
        const size_t row = (size_t)by * 128 + ty * 8 + i;
#pragma unroll
        for (int j = 0; j < 8; j++) {
            const int col = bx * 128 + tx * 8 + j;
            C[row * N + col] = acc[i][j] + bias[col];
        }
    }
}

// ---------------- fused windowed attention: one CTA per (window, head) ----------------
// qkv layout: [M_TOT, 3*CDIM]; q at col h*HD, k at CDIM + h*HD, v at 2*CDIM + h*HD.
// scale = NUM_HEADS**-0.5 = 0.25 (faithful to the reference's num_heads scaling).
__global__ __launch_bounds__(256)
void attn_kernel(const float* __restrict__ qkv,
                 const float* __restrict__ bias_table,  // [(2W-1)^2, NH]
                 const int*   __restrict__ rel_idx,     // [NTOK*NTOK]
                 float* __restrict__ out)               // [M_TOT, CDIM]
{
    const int b = blockIdx.x;
    const int h = blockIdx.y;
    const int tid = threadIdx.x;

    __shared__ float qs[NTOK][HD + 1];
    __shared__ float ks[NTOK][HD + 1];
    __shared__ float vs[NTOK][HD + 1];
    __shared__ float sc[NTOK][NTOK + 1];

    const size_t rowbase = (size_t)b * NTOK;

    for (int idx = tid; idx < NTOK * HD; idx += blockDim.x) {
        const int i = idx / HD, d = idx % HD;
        const size_t base = (rowbase + i) * (3 * CDIM) + h * HD + d;
        qs[i][d] = qkv[base] * 0.25f;
        ks[i][d] = qkv[base + CDIM];
        vs[i][d] = qkv[base + 2 * CDIM];
    }
    __syncthreads();

    for (int idx = tid; idx < NTOK * NTOK; idx += blockDim.x) {
        const int i = idx / NTOK, j = idx % NTOK;
        float s = 0.f;
#pragma unroll
        for (int d = 0; d < HD; d++) s = fmaf(qs[i][d], ks[j][d], s);
        s += bias_table[rel_idx[idx] * NH + h];
        sc[i][j] = s;
    }
    __syncthreads();

    if (tid < NTOK) {
        float m = -1e30f;
#pragma unroll 7
        for (int j = 0; j < NTOK; j++) m = fmaxf(m, sc[tid][j]);
        float sum = 0.f;
#pragma unroll 7
        for (int j = 0; j < NTOK; j++) {
            const float e = __expf(sc[tid][j] - m);
            sc[tid][j] = e;
            sum += e;
        }
        const float inv = 1.f / sum;
#pragma unroll 7
        for (int j = 0; j < NTOK; j++) sc[tid][j] *= inv;
    }
    __syncthreads();

    for (int idx = tid; idx < NTOK * HD; idx += blockDim.x) {
        const int i = idx / HD, d = idx % HD;
        float s = 0.f;
#pragma unroll
        for (int j = 0; j < NTOK; j++) s = fmaf(sc[i][j], vs[j][d], s);
        out[(rowbase + i) * CDIM + h * HD + d] = s;
    }
}

// ---------------- launch ----------------
extern "C" void kernel_launch(void* const* d_in, const int* in_sizes, int n_in,
                              void* d_out, int out_size)
{
    const float* x          = (const float*)d_in[0];
    const float* w_qkv      = (const float*)d_in[1];
    const float* b_qkv      = (const float*)d_in[2];
    const float* w_gamma    = (const float*)d_in[3];
    const float* b_gamma    = (const float*)d_in[4];
    const float* w_proj     = (const float*)d_in[5];
    const float* b_proj     = (const float*)d_in[6];
    const float* bias_table = (const float*)d_in[7];
    const int*   rel_idx    = (const int*)d_in[8];
    float* out = (float*)d_out;

    float *qkv_buf, *buf1, *buf2;
    cudaGetSymbolAddress((void**)&qkv_buf, g_qkv);
    cudaGetSymbolAddress((void**)&buf1, g_buf1);
    cudaGetSymbolAddress((void**)&buf2, g_buf2);

    // 1) qkv = x @ w_qkv^T + b_qkv   [100352, 1536]
    {
        dim3 grid(3 * CDIM / 128, M_TOT / 128);
        sgemm_nt_bias<<<grid, 256>>>(x, w_qkv, b_qkv, qkv_buf, M_TOT, 3 * CDIM, CDIM);
    }
    // 2) fused windowed attention -> buf1 [100352, 512]
    {
        dim3 grid(BATCH, NH);
        attn_kernel<<<grid, 256>>>(qkv_buf, bias_table, rel_idx, buf1);
    }
    // 3) gamma = buf1 @ w_gamma^T + b_gamma -> buf2
    {
        dim3 grid(CDIM / 128, M_TOT / 128);
        sgemm_nt_bias<<<grid, 256>>>(buf1, w_gamma, b_gamma, buf2, M_TOT, CDIM, CDIM);
    }
    // 4) out = buf2 @ w_proj^T + b_proj -> d_out
    {
        dim3 grid(CDIM / 128, M_TOT / 128);
        sgemm_nt_bias<<<grid, 256>>>(buf2, w_proj, b_proj, out, M_TOT, CDIM, CDIM);
    }
}

// round 6
// speedup vs baseline: 2.2292x; 2.2292x over previous
#include <cuda_runtime.h>
#include <cuda_bf16.h>
#include <cstdint>
#include <cstddef>

#define WIN 7
#define NTOK 49
#define NH 16
#define HD 32
#define CDIM 512
#define BATCH 2048
#define M_TOT (BATCH * NTOK)   // 100352 = 784 * 128
#define KEFF 1536              // 3 * 512 (hi|lo|hi concat)

// ---------------- scratch (static device globals; no allocations) ----------------
__device__ float g_qkv [(size_t)M_TOT * 3 * CDIM];          // 616 MB
__device__ float g_buf1[(size_t)M_TOT * CDIM];              // 205 MB
__device__ float g_buf2[(size_t)M_TOT * CDIM];              // 205 MB
__device__ __nv_bfloat16 g_A3[(size_t)M_TOT * KEFF];        // 308 MB
__device__ __nv_bfloat16 g_B3[(size_t)3 * CDIM * KEFF];     // 4.7 MB

// =====================================================================
// helpers
// =====================================================================
__device__ __forceinline__ uint32_t smem_u32(const void* p) {
    uint32_t a;
    asm("{ .reg .u64 t; cvta.to.shared.u64 t, %1; cvt.u32.u64 %0, t; }" : "=r"(a) : "l"(p));
    return a;
}
__device__ __forceinline__ void cp16(uint32_t s, const void* g) {
    asm volatile("cp.async.cg.shared.global [%0], [%1], 16;" :: "r"(s), "l"(g));
}

// =====================================================================
// split: dst row layout depends on mode.
//   mode 0 (A-side): [hi | lo | hi]
//   mode 1 (B-side): [hi | hi | lo]
// src is [rows, 512] fp32; dst is [rows, 1536] bf16.
// =====================================================================
__global__ void split3_kernel(const float* __restrict__ src,
                              __nv_bfloat16* __restrict__ dst,
                              int n4, int mode)
{
    int i = blockIdx.x * blockDim.x + threadIdx.x;
    if (i >= n4) return;
    const int row = i >> 7;            // 512/4 = 128 float4 per row
    const int col = (i & 127) * 4;
    float4 v = ((const float4*)src)[i];

    __nv_bfloat16 h0 = __float2bfloat16_rn(v.x);
    __nv_bfloat16 h1 = __float2bfloat16_rn(v.y);
    __nv_bfloat16 h2 = __float2bfloat16_rn(v.z);
    __nv_bfloat16 h3 = __float2bfloat16_rn(v.w);
    __nv_bfloat16 l0 = __float2bfloat16_rn(v.x - __bfloat162float(h0));
    __nv_bfloat16 l1 = __float2bfloat16_rn(v.y - __bfloat162float(h1));
    __nv_bfloat16 l2 = __float2bfloat16_rn(v.z - __bfloat162float(h2));
    __nv_bfloat16 l3 = __float2bfloat16_rn(v.w - __bfloat162float(h3));

    uint32_t hA = (__bfloat16_as_ushort(h1) << 16) | __bfloat16_as_ushort(h0);
    uint32_t hB = (__bfloat16_as_ushort(h3) << 16) | __bfloat16_as_ushort(h2);
    uint32_t lA = (__bfloat16_as_ushort(l1) << 16) | __bfloat16_as_ushort(l0);
    uint32_t lB = (__bfloat16_as_ushort(l3) << 16) | __bfloat16_as_ushort(l2);

    uint32_t* base = (uint32_t*)(dst + (size_t)row * KEFF + col);
    // segment offsets in uint32 units (2 bf16 each): 512 elems = 256 u32
    if (mode == 0) {
        base[0] = hA;            base[1] = hB;            // hi @ 0
        base[256] = lA;          base[257] = lB;          // lo @ 512
        base[512] = hA;          base[513] = hB;          // hi @ 1024
    } else {
        base[0] = hA;            base[1] = hB;            // hi @ 0
        base[256] = hA;          base[257] = hB;          // hi @ 512
        base[512] = lA;          base[513] = lB;          // lo @ 1024
    }
}

// =====================================================================
// BF16 GEMM via mma.sync:  C[M,N] = A3[M,1536] * B3[N,1536]^T + bias[N]
// CTA tile 128x128, BK=64, 3-stage cp.async, 256 threads (8 warps 2x4),
// warp tile 64x32, XOR-swizzled smem + ldmatrix.
// =====================================================================
#define BKB 64
#define NKIT (KEFF / BKB)            // 24
#define STAGE_A (128 * BKB * 2)      // 16384
#define STAGE_BYTES (2 * STAGE_A)    // 32768 (A then B)
#define GEMM_SMEM (3 * STAGE_BYTES)  // 98304

__global__ void __launch_bounds__(256)
gemm_bf16x3(const __nv_bfloat16* __restrict__ A,
            const __nv_bfloat16* __restrict__ B,
            const float* __restrict__ bias,
            float* __restrict__ C, int N)
{
    extern __shared__ char smem[];
    const uint32_t sb = smem_u32(smem);
    const int tid  = threadIdx.x;
    const int lane = tid & 31;
    const int wid  = tid >> 5;
    const int wm   = wid >> 2;   // 0..1
    const int wn   = wid & 3;    // 0..3

    const __nv_bfloat16* Ag = A + (size_t)blockIdx.y * 128 * KEFF;
    const __nv_bfloat16* Bg = B + (size_t)blockIdx.x * 128 * KEFF;

    const int lr = tid >> 3;        // 0..31 (+32*i)
    const int lc = tid & 7;         // chunk 0..7

    auto load_stage = [&](int kt, int slot) {
        const uint32_t base = sb + (uint32_t)slot * STAGE_BYTES;
        const int kof = kt * BKB;
#pragma unroll
        for (int i = 0; i < 4; i++) {
            const int r = lr + i * 32;
            const uint32_t so = (uint32_t)r * 128 + (uint32_t)((lc ^ (r & 7)) << 4);
            cp16(base + so,           Ag + (size_t)r * KEFF + kof + lc * 8);
            cp16(base + STAGE_A + so, Bg + (size_t)r * KEFF + kof + lc * 8);
        }
    };

    float acc[4][4][4];
#pragma unroll
    for (int a = 0; a < 4; a++)
#pragma unroll
        for (int b = 0; b < 4; b++)
#pragma unroll
            for (int c = 0; c < 4; c++) acc[a][b][c] = 0.f;

    load_stage(0, 0); asm volatile("cp.async.commit_group;" ::: "memory");
    load_stage(1, 1); asm volatile("cp.async.commit_group;" ::: "memory");

    // per-thread ldmatrix row/chunk components
    const int rA0 = wm * 64 + (lane & 15);   // + im*16
    const int cAh = lane >> 4;               // 0..1
    const int rB0 = wn * 32 + (lane & 7);    // + in*8
    const int cBh = (lane >> 3) & 1;         // 0..1

    for (int kt = 0; kt < NKIT; kt++) {
        asm volatile("cp.async.wait_group 1;" ::: "memory");
        __syncthreads();
        if (kt + 2 < NKIT) load_stage(kt + 2, (kt + 2) % 3);
        asm volatile("cp.async.commit_group;" ::: "memory");

        const uint32_t base = sb + (uint32_t)(kt % 3) * STAGE_BYTES;
#pragma unroll
        for (int kk = 0; kk < 4; kk++) {
            uint32_t afr[4][4];
#pragma unroll
            for (int im = 0; im < 4; im++) {
                const int r = rA0 + im * 16;
                const uint32_t addr = base + (uint32_t)r * 128 +
                    (uint32_t)(((2 * kk + cAh) ^ (r & 7)) << 4);
                asm volatile("ldmatrix.sync.aligned.m8n8.x4.shared.b16 {%0,%1,%2,%3}, [%4];"
                    : "=r"(afr[im][0]), "=r"(afr[im][1]), "=r"(afr[im][2]), "=r"(afr[im][3])
                    : "r"(addr));
            }
            uint32_t bfr[4][2];
#pragma unroll
            for (int in = 0; in < 4; in++) {
                const int r = rB0 + in * 8;
                const uint32_t addr = base + STAGE_A + (uint32_t)r * 128 +
                    (uint32_t)(((2 * kk + cBh) ^ (r & 7)) << 4);
                asm volatile("ldmatrix.sync.aligned.m8n8.x2.shared.b16 {%0,%1}, [%2];"
                    : "=r"(bfr[in][0]), "=r"(bfr[in][1]) : "r"(addr));
            }
#pragma unroll
            for (int im = 0; im < 4; im++)
#pragma unroll
                for (int in = 0; in < 4; in++) {
                    asm volatile(
                        "mma.sync.aligned.m16n8k16.row.col.f32.bf16.bf16.f32 "
                        "{%0,%1,%2,%3}, {%4,%5,%6,%7}, {%8,%9}, {%0,%1,%2,%3};"
                        : "+f"(acc[im][in][0]), "+f"(acc[im][in][1]),
                          "+f"(acc[im][in][2]), "+f"(acc[im][in][3])
                        : "r"(afr[im][0]), "r"(afr[im][1]), "r"(afr[im][2]), "r"(afr[im][3]),
                          "r"(bfr[in][0]), "r"(bfr[in][1]));
                }
        }
    }

    // ---- epilogue: fragments -> C (+bias) ----
    const int mBase = blockIdx.y * 128 + wm * 64;
    const int nBase = blockIdx.x * 128 + wn * 32;
    const int rr = lane >> 2;
    const int cc = (lane & 3) * 2;
#pragma unroll
    for (int im = 0; im < 4; im++) {
#pragma unroll
        for (int in = 0; in < 4; in++) {
            const int row = mBase + im * 16 + rr;
            const int col = nBase + in * 8 + cc;
            const float bx = bias[col], by = bias[col + 1];
            float2 v0 = make_float2(acc[im][in][0] + bx, acc[im][in][1] + by);
            float2 v1 = make_float2(acc[im][in][2] + bx, acc[im][in][3] + by);
            *(float2*)(C + (size_t)row * N + col) = v0;
            *(float2*)(C + (size_t)(row + 8) * N + col) = v1;
        }
    }
}

// =====================================================================
// fused windowed attention: one CTA per (window, head)
// =====================================================================
__global__ __launch_bounds__(256)
void attn_kernel(const float* __restrict__ qkv,
                 const float* __restrict__ bias_table,
                 const int*   __restrict__ rel_idx,
                 float* __restrict__ out)
{
    const int b = blockIdx.x;
    const int h = blockIdx.y;
    const int tid = threadIdx.x;

    __shared__ float qs[NTOK][HD + 1];
    __shared__ float ks[NTOK][HD + 1];
    __shared__ float vs[NTOK][HD + 1];
    __shared__ float sc[NTOK][NTOK + 1];

    const size_t rowbase = (size_t)b * NTOK;

    for (int idx = tid; idx < NTOK * HD; idx += blockDim.x) {
        const int i = idx / HD, d = idx % HD;
        const size_t base = (rowbase + i) * (3 * CDIM) + h * HD + d;
        qs[i][d] = qkv[base] * 0.25f;
        ks[i][d] = qkv[base + CDIM];
        vs[i][d] = qkv[base + 2 * CDIM];
    }
    __syncthreads();

    for (int idx = tid; idx < NTOK * NTOK; idx += blockDim.x) {
        const int i = idx / NTOK, j = idx % NTOK;
        float s = 0.f;
#pragma unroll
        for (int d = 0; d < HD; d++) s = fmaf(qs[i][d], ks[j][d], s);
        s += bias_table[rel_idx[idx] * NH + h];
        sc[i][j] = s;
    }
    __syncthreads();

    if (tid < NTOK) {
        float m = -1e30f;
#pragma unroll 7
        for (int j = 0; j < NTOK; j++) m = fmaxf(m, sc[tid][j]);
        float sum = 0.f;
#pragma unroll 7
        for (int j = 0; j < NTOK; j++) {
            const float e = __expf(sc[tid][j] - m);
            sc[tid][j] = e;
            sum += e;
        }
        const float inv = 1.f / sum;
#pragma unroll 7
        for (int j = 0; j < NTOK; j++) sc[tid][j] *= inv;
    }
    __syncthreads();

    for (int idx = tid; idx < NTOK * HD; idx += blockDim.x) {
        const int i = idx / HD, d = idx % HD;
        float s = 0.f;
#pragma unroll
        for (int j = 0; j < NTOK; j++) s = fmaf(sc[i][j], vs[j][d], s);
        out[(rowbase + i) * CDIM + h * HD + d] = s;
    }
}

// =====================================================================
// launch
// =====================================================================
static inline void launch_split(const float* src, __nv_bfloat16* dst,
                                size_t nelem, int mode) {
    const int n4 = (int)(nelem / 4);
    split3_kernel<<<(n4 + 255) / 256, 256>>>(src, dst, n4, mode);
}

extern "C" void kernel_launch(void* const* d_in, const int* in_sizes, int n_in,
                              void* d_out, int out_size)
{
    const float* x          = (const float*)d_in[0];
    const float* w_qkv      = (const float*)d_in[1];
    const float* b_qkv      = (const float*)d_in[2];
    const float* w_gamma    = (const float*)d_in[3];
    const float* b_gamma    = (const float*)d_in[4];
    const float* w_proj     = (const float*)d_in[5];
    const float* b_proj     = (const float*)d_in[6];
    const float* bias_table = (const float*)d_in[7];
    const int*   rel_idx    = (const int*)d_in[8];
    float* out = (float*)d_out;

    float *qkv_buf, *buf1, *buf2;
    __nv_bfloat16 *A3, *B3;
    cudaGetSymbolAddress((void**)&qkv_buf, g_qkv);
    cudaGetSymbolAddress((void**)&buf1, g_buf1);
    cudaGetSymbolAddress((void**)&buf2, g_buf2);
    cudaGetSymbolAddress((void**)&A3, g_A3);
    cudaGetSymbolAddress((void**)&B3, g_B3);

    cudaFuncSetAttribute(gemm_bf16x3, cudaFuncAttributeMaxDynamicSharedMemorySize, GEMM_SMEM);

    // 1) qkv = x @ w_qkv^T + b_qkv   [100352, 1536]
    launch_split(x, A3, (size_t)M_TOT * CDIM, 0);
    launch_split(w_qkv, B3, (size_t)3 * CDIM * CDIM, 1);
    {
        dim3 grid(3 * CDIM / 128, M_TOT / 128);
        gemm_bf16x3<<<grid, 256, GEMM_SMEM>>>(A3, B3, b_qkv, qkv_buf, 3 * CDIM);
    }
    // 2) fused windowed attention -> buf1 [100352, 512]
    {
        dim3 grid(BATCH, NH);
        attn_kernel<<<grid, 256>>>(qkv_buf, bias_table, rel_idx, buf1);
    }
    // 3) gamma = buf1 @ w_gamma^T + b_gamma -> buf2
    launch_split(buf1, A3, (size_t)M_TOT * CDIM, 0);
    launch_split(w_gamma, B3, (size_t)CDIM * CDIM, 1);
    {
        dim3 grid(CDIM / 128, M_TOT / 128);
        gemm_bf16x3<<<grid, 256, GEMM_SMEM>>>(A3, B3, b_gamma, buf2, CDIM);
    }
    // 4) out = buf2 @ w_proj^T + b_proj -> d_out
    launch_split(buf2, A3, (size_t)M_TOT * CDIM, 0);
    launch_split(w_proj, B3, (size_t)CDIM * CDIM, 1);
    {
        dim3 grid(CDIM / 128, M_TOT / 128);
        gemm_bf16x3<<<grid, 256, GEMM_SMEM>>>(A3, B3, b_proj, out, CDIM);
    }
}

// round 7
// speedup vs baseline: 2.5774x; 1.1562x over previous
#include <cuda_runtime.h>
#include <cuda_bf16.h>
#include <cstdint>
#include <cstddef>

#define WIN 7
#define NTOK 49
#define NH 16
#define HD 32
#define CDIM 512
#define BATCH 2048
#define M_TOT (BATCH * NTOK)   // 100352 = 784 * 128
#define KEFF 1536              // 3 * 512 (hi|lo|hi concat)

// ---------------- scratch (static device globals; no allocations) ----------------
__device__ float g_qkv [(size_t)M_TOT * 3 * CDIM];          // 616 MB
__device__ __nv_bfloat16 g_A3 [(size_t)M_TOT * KEFF];       // 308 MB
__device__ __nv_bfloat16 g_A3b[(size_t)M_TOT * KEFF];       // 308 MB
__device__ __nv_bfloat16 g_B3 [(size_t)3 * CDIM * KEFF];    // 4.7 MB

// =====================================================================
// helpers
// =====================================================================
__device__ __forceinline__ uint32_t smem_u32(const void* p) {
    uint32_t a;
    asm("{ .reg .u64 t; cvta.to.shared.u64 t, %1; cvt.u32.u64 %0, t; }" : "=r"(a) : "l"(p));
    return a;
}
__device__ __forceinline__ void cp16(uint32_t s, const void* g) {
    asm volatile("cp.async.cg.shared.global [%0], [%1], 16;" :: "r"(s), "l"(g));
}
__device__ __forceinline__ uint32_t pack_bf16(__nv_bfloat16 a, __nv_bfloat16 b) {
    return ((uint32_t)__bfloat16_as_ushort(b) << 16) | __bfloat16_as_ushort(a);
}
__device__ __forceinline__ void split1(float v, __nv_bfloat16& h, __nv_bfloat16& l) {
    h = __float2bfloat16_rn(v);
    l = __float2bfloat16_rn(v - __bfloat162float(h));
}

// =====================================================================
// split: mode 0 (A-side): [hi | lo | hi]   mode 1 (B-side): [hi | hi | lo]
// src [rows, 512] fp32 -> dst [rows, 1536] bf16.
// =====================================================================
__global__ void split3_kernel(const float* __restrict__ src,
                              __nv_bfloat16* __restrict__ dst,
                              int n4, int mode)
{
    int i = blockIdx.x * blockDim.x + threadIdx.x;
    if (i >= n4) return;
    const int row = i >> 7;
    const int col = (i & 127) * 4;
    float4 v = ((const float4*)src)[i];

    __nv_bfloat16 h0, h1, h2, h3, l0, l1, l2, l3;
    split1(v.x, h0, l0); split1(v.y, h1, l1);
    split1(v.z, h2, l2); split1(v.w, h3, l3);

    uint32_t hA = pack_bf16(h0, h1), hB = pack_bf16(h2, h3);
    uint32_t lA = pack_bf16(l0, l1), lB = pack_bf16(l2, l3);

    uint32_t* base = (uint32_t*)(dst + (size_t)row * KEFF + col);
    if (mode == 0) {
        base[0] = hA;   base[1] = hB;
        base[256] = lA; base[257] = lB;
        base[512] = hA; base[513] = hB;
    } else {
        base[0] = hA;   base[1] = hB;
        base[256] = hA; base[257] = hB;
        base[512] = lA; base[513] = lB;
    }
}

// =====================================================================
// BF16 GEMM via mma.sync:  C[M,N] = A3[M,1536] * B3[N,1536]^T + bias[N]
// CTA tile 128x128, BK=64, 3-stage cp.async, 256 threads (8 warps 2x4).
// split_out=0: write fp32 Cf[M,N].  split_out=1: write bf16 hi|lo|hi Cs[M,1536].
// =====================================================================
#define BKB 64
#define NKIT (KEFF / BKB)            // 24
#define STAGE_A (128 * BKB * 2)      // 16384
#define STAGE_BYTES (2 * STAGE_A)    // 32768
#define GEMM_SMEM (3 * STAGE_BYTES)  // 98304

__global__ void __launch_bounds__(256)
gemm_bf16x3(const __nv_bfloat16* __restrict__ A,
            const __nv_bfloat16* __restrict__ B,
            const float* __restrict__ bias,
            float* __restrict__ Cf,
            __nv_bfloat16* __restrict__ Cs,
            int N, int split_out)
{
    extern __shared__ char smem[];
    const uint32_t sb = smem_u32(smem);
    const int tid  = threadIdx.x;
    const int lane = tid & 31;
    const int wid  = tid >> 5;
    const int wm   = wid >> 2;
    const int wn   = wid & 3;

    const __nv_bfloat16* Ag = A + (size_t)blockIdx.y * 128 * KEFF;
    const __nv_bfloat16* Bg = B + (size_t)blockIdx.x * 128 * KEFF;

    const int lr = tid >> 3;
    const int lc = tid & 7;

    auto load_stage = [&](int kt, int slot) {
        const uint32_t base = sb + (uint32_t)slot * STAGE_BYTES;
        const int kof = kt * BKB;
#pragma unroll
        for (int i = 0; i < 4; i++) {
            const int r = lr + i * 32;
            const uint32_t so = (uint32_t)r * 128 + (uint32_t)((lc ^ (r & 7)) << 4);
            cp16(base + so,           Ag + (size_t)r * KEFF + kof + lc * 8);
            cp16(base + STAGE_A + so, Bg + (size_t)r * KEFF + kof + lc * 8);
        }
    };

    float acc[4][4][4];
#pragma unroll
    for (int a = 0; a < 4; a++)
#pragma unroll
        for (int b = 0; b < 4; b++)
#pragma unroll
            for (int c = 0; c < 4; c++) acc[a][b][c] = 0.f;

    load_stage(0, 0); asm volatile("cp.async.commit_group;" ::: "memory");
    load_stage(1, 1); asm volatile("cp.async.commit_group;" ::: "memory");

    const int rA0 = wm * 64 + (lane & 15);
    const int cAh = lane >> 4;
    const int rB0 = wn * 32 + (lane & 7);
    const int cBh = (lane >> 3) & 1;

    for (int kt = 0; kt < NKIT; kt++) {
        asm volatile("cp.async.wait_group 1;" ::: "memory");
        __syncthreads();
        if (kt + 2 < NKIT) load_stage(kt + 2, (kt + 2) % 3);
        asm volatile("cp.async.commit_group;" ::: "memory");

        const uint32_t base = sb + (uint32_t)(kt % 3) * STAGE_BYTES;
#pragma unroll
        for (int kk = 0; kk < 4; kk++) {
            uint32_t afr[4][4];
#pragma unroll
            for (int im = 0; im < 4; im++) {
                const int r = rA0 + im * 16;
                const uint32_t addr = base + (uint32_t)r * 128 +
                    (uint32_t)(((2 * kk + cAh) ^ (r & 7)) << 4);
                asm volatile("ldmatrix.sync.aligned.m8n8.x4.shared.b16 {%0,%1,%2,%3}, [%4];"
                    : "=r"(afr[im][0]), "=r"(afr[im][1]), "=r"(afr[im][2]), "=r"(afr[im][3])
                    : "r"(addr));
            }
            uint32_t bfr[4][2];
#pragma unroll
            for (int in = 0; in < 4; in++) {
                const int r = rB0 + in * 8;
                const uint32_t addr = base + STAGE_A + (uint32_t)r * 128 +
                    (uint32_t)(((2 * kk + cBh) ^ (r & 7)) << 4);
                asm volatile("ldmatrix.sync.aligned.m8n8.x2.shared.b16 {%0,%1}, [%2];"
                    : "=r"(bfr[in][0]), "=r"(bfr[in][1]) : "r"(addr));
            }
#pragma unroll
            for (int im = 0; im < 4; im++)
#pragma unroll
                for (int in = 0; in < 4; in++) {
                    asm volatile(
                        "mma.sync.aligned.m16n8k16.row.col.f32.bf16.bf16.f32 "
                        "{%0,%1,%2,%3}, {%4,%5,%6,%7}, {%8,%9}, {%0,%1,%2,%3};"
                        : "+f"(acc[im][in][0]), "+f"(acc[im][in][1]),
                          "+f"(acc[im][in][2]), "+f"(acc[im][in][3])
                        : "r"(afr[im][0]), "r"(afr[im][1]), "r"(afr[im][2]), "r"(afr[im][3]),
                          "r"(bfr[in][0]), "r"(bfr[in][1]));
                }
        }
    }

    // ---- epilogue ----
    const int mBase = blockIdx.y * 128 + wm * 64;
    const int nBase = blockIdx.x * 128 + wn * 32;
    const int rr = lane >> 2;
    const int cc = (lane & 3) * 2;

    if (!split_out) {
#pragma unroll
        for (int im = 0; im < 4; im++)
#pragma unroll
            for (int in = 0; in < 4; in++) {
                const int row = mBase + im * 16 + rr;
                const int col = nBase + in * 8 + cc;
                const float bx = bias[col], by = bias[col + 1];
                *(float2*)(Cf + (size_t)row * N + col) =
                    make_float2(acc[im][in][0] + bx, acc[im][in][1] + by);
                *(float2*)(Cf + (size_t)(row + 8) * N + col) =
                    make_float2(acc[im][in][2] + bx, acc[im][in][3] + by);
            }
    } else {
#pragma unroll
        for (int im = 0; im < 4; im++)
#pragma unroll
            for (int in = 0; in < 4; in++) {
                const int row = mBase + im * 16 + rr;
                const int col = nBase + in * 8 + cc;
                const float bx = bias[col], by = bias[col + 1];
                float v0 = acc[im][in][0] + bx, v1 = acc[im][in][1] + by;
                float v2 = acc[im][in][2] + bx, v3 = acc[im][in][3] + by;
                __nv_bfloat16 h0, h1, h2, h3, l0, l1, l2, l3;
                split1(v0, h0, l0); split1(v1, h1, l1);
                split1(v2, h2, l2); split1(v3, h3, l3);
                uint32_t* p0 = (uint32_t*)(Cs + (size_t)row * KEFF + col);
                p0[0]   = pack_bf16(h0, h1);
                p0[256] = pack_bf16(l0, l1);
                p0[512] = pack_bf16(h0, h1);
                uint32_t* p1 = (uint32_t*)(Cs + (size_t)(row + 8) * KEFF + col);
                p1[0]   = pack_bf16(h2, h3);
                p1[256] = pack_bf16(l2, l3);
                p1[512] = pack_bf16(h2, h3);
            }
    }
}

// =====================================================================
// fused windowed attention (register-blocked), writes bf16 hi|lo|hi split
// =====================================================================
__global__ __launch_bounds__(256)
void attn_kernel(const float* __restrict__ qkv,
                 const float* __restrict__ bias_table,
                 const int*   __restrict__ rel_idx,
                 __nv_bfloat16* __restrict__ outs)   // [M_TOT, 1536]
{
    const int b  = blockIdx.x;
    const int hh = blockIdx.y;
    const int tid = threadIdx.x;

    __shared__ float qs[NTOK][HD + 1];
    __shared__ float ks[NTOK][HD + 1];
    __shared__ float vs[NTOK][HD + 1];
    __shared__ float sc[NTOK][NTOK + 1];

    const size_t rowbase = (size_t)b * NTOK;

    for (int idx = tid; idx < NTOK * HD; idx += 256) {
        const int i = idx >> 5, d = idx & 31;
        const size_t base = (rowbase + i) * (3 * CDIM) + hh * HD + d;
        qs[i][d] = qkv[base] * 0.25f;
        ks[i][d] = qkv[base + CDIM];
        vs[i][d] = qkv[base + 2 * CDIM];
    }
    __syncthreads();

    // ---- scores, 2x2 register blocking: 25x25 = 625 items ----
    for (int it = tid; it < 625; it += 256) {
        const int pi = it / 25, pj = it - pi * 25;
        const int i0 = 2 * pi, j0 = 2 * pj;
        const int i1 = (i0 + 1 < NTOK) ? i0 + 1 : i0;
        const int j1 = (j0 + 1 < NTOK) ? j0 + 1 : j0;
        float s00 = 0.f, s01 = 0.f, s10 = 0.f, s11 = 0.f;
#pragma unroll
        for (int d = 0; d < HD; d++) {
            const float qa = qs[i0][d], qb = qs[i1][d];
            const float ka = ks[j0][d], kb = ks[j1][d];
            s00 = fmaf(qa, ka, s00); s01 = fmaf(qa, kb, s01);
            s10 = fmaf(qb, ka, s10); s11 = fmaf(qb, kb, s11);
        }
        sc[i0][j0] = s00 + bias_table[rel_idx[i0 * NTOK + j0] * NH + hh];
        if (j0 + 1 < NTOK)
            sc[i0][j1] = s01 + bias_table[rel_idx[i0 * NTOK + j1] * NH + hh];
        if (i0 + 1 < NTOK) {
            sc[i1][j0] = s10 + bias_table[rel_idx[i1 * NTOK + j0] * NH + hh];
            if (j0 + 1 < NTOK)
                sc[i1][j1] = s11 + bias_table[rel_idx[i1 * NTOK + j1] * NH + hh];
        }
    }
    __syncthreads();

    // ---- softmax rows ----
    if (tid < NTOK) {
        float m = -1e30f;
#pragma unroll 7
        for (int j = 0; j < NTOK; j++) m = fmaxf(m, sc[tid][j]);
        float sum = 0.f;
#pragma unroll 7
        for (int j = 0; j < NTOK; j++) {
            const float e = __expf(sc[tid][j] - m);
            sc[tid][j] = e;
            sum += e;
        }
        const float inv = 1.f / sum;
#pragma unroll 7
        for (int j = 0; j < NTOK; j++) sc[tid][j] *= inv;
    }
    __syncthreads();

    // ---- AV, 2x4 blocking: 25 i-pairs x 8 d-quads = 200 items ----
    if (tid < 200) {
        const int pi = tid >> 3, pd = tid & 7;
        const int i0 = 2 * pi, d0 = 4 * pd;
        const int i1 = (i0 + 1 < NTOK) ? i0 + 1 : i0;
        float a0 = 0.f, a1 = 0.f, a2 = 0.f, a3 = 0.f;
        float b0 = 0.f, b1 = 0.f, b2 = 0.f, b3 = 0.f;
#pragma unroll
        for (int j = 0; j < NTOK; j++) {
            const float pa = sc[i0][j], pb = sc[i1][j];
            const float v0 = vs[j][d0], v1 = vs[j][d0 + 1];
            const float v2 = vs[j][d0 + 2], v3 = vs[j][d0 + 3];
            a0 = fmaf(pa, v0, a0); a1 = fmaf(pa, v1, a1);
            a2 = fmaf(pa, v2, a2); a3 = fmaf(pa, v3, a3);
            b0 = fmaf(pb, v0, b0); b1 = fmaf(pb, v1, b1);
            b2 = fmaf(pb, v2, b2); b3 = fmaf(pb, v3, b3);
        }
        // write split bf16 rows
        {
            __nv_bfloat16 h0, h1, h2, h3, l0, l1, l2, l3;
            split1(a0, h0, l0); split1(a1, h1, l1);
            split1(a2, h2, l2); split1(a3, h3, l3);
            uint32_t* p = (uint32_t*)(outs + (rowbase + i0) * KEFF + hh * HD + d0);
            p[0] = pack_bf16(h0, h1);   p[1] = pack_bf16(h2, h3);
            p[256] = pack_bf16(l0, l1); p[257] = pack_bf16(l2, l3);
            p[512] = pack_bf16(h0, h1); p[513] = pack_bf16(h2, h3);
        }
        if (i0 + 1 < NTOK) {
            __nv_bfloat16 h0, h1, h2, h3, l0, l1, l2, l3;
            split1(b0, h0, l0); split1(b1, h1, l1);
            split1(b2, h2, l2); split1(b3, h3, l3);
            uint32_t* p = (uint32_t*)(outs + (rowbase + i1) * KEFF + hh * HD + d0);
            p[0] = pack_bf16(h0, h1);   p[1] = pack_bf16(h2, h3);
            p[256] = pack_bf16(l0, l1); p[257] = pack_bf16(l2, l3);
            p[512] = pack_bf16(h0, h1); p[513] = pack_bf16(h2, h3);
        }
    }
}

// =====================================================================
// launch
// =====================================================================
static inline void launch_split(const float* src, __nv_bfloat16* dst,
                                size_t nelem, int mode) {
    const int n4 = (int)(nelem / 4);
    split3_kernel<<<(n4 + 255) / 256, 256>>>(src, dst, n4, mode);
}

extern "C" void kernel_launch(void* const* d_in, const int* in_sizes, int n_in,
                              void* d_out, int out_size)
{
    const float* x          = (const float*)d_in[0];
    const float* w_qkv      = (const float*)d_in[1];
    const float* b_qkv      = (const float*)d_in[2];
    const float* w_gamma    = (const float*)d_in[3];
    const float* b_gamma    = (const float*)d_in[4];
    const float* w_proj     = (const float*)d_in[5];
    const float* b_proj     = (const float*)d_in[6];
    const float* bias_table = (const float*)d_in[7];
    const int*   rel_idx    = (const int*)d_in[8];
    float* out = (float*)d_out;

    float* qkv_buf;
    __nv_bfloat16 *A3, *A3b, *B3;
    cudaGetSymbolAddress((void**)&qkv_buf, g_qkv);
    cudaGetSymbolAddress((void**)&A3,  g_A3);
    cudaGetSymbolAddress((void**)&A3b, g_A3b);
    cudaGetSymbolAddress((void**)&B3,  g_B3);

    cudaFuncSetAttribute(gemm_bf16x3, cudaFuncAttributeMaxDynamicSharedMemorySize, GEMM_SMEM);

    // 1) qkv = x @ w_qkv^T + b_qkv   [100352, 1536] fp32
    launch_split(x, A3, (size_t)M_TOT * CDIM, 0);
    launch_split(w_qkv, B3, (size_t)3 * CDIM * CDIM, 1);
    {
        dim3 grid(3 * CDIM / 128, M_TOT / 128);
        gemm_bf16x3<<<grid, 256, GEMM_SMEM>>>(A3, B3, b_qkv, qkv_buf, nullptr, 3 * CDIM, 0);
    }
    // 2) attention -> A3b (bf16 split layout, ready for next GEMM)
    {
        dim3 grid(BATCH, NH);
        attn_kernel<<<grid, 256>>>(qkv_buf, bias_table, rel_idx, A3b);
    }
    // 3) gamma = attn_out @ w_gamma^T + b_gamma -> A3 (bf16 split layout)
    launch_split(w_gamma, B3, (size_t)CDIM * CDIM, 1);
    {
        dim3 grid(CDIM / 128, M_TOT / 128);
        gemm_bf16x3<<<grid, 256, GEMM_SMEM>>>(A3b, B3, b_gamma, nullptr, A3, CDIM, 1);
    }
    // 4) out = gamma_out @ w_proj^T + b_proj -> d_out fp32
    launch_split(w_proj, B3, (size_t)CDIM * CDIM, 1);
    {
        dim3 grid(CDIM / 128, M_TOT / 128);
        gemm_bf16x3<<<grid, 256, GEMM_SMEM>>>(A3, B3, b_proj, out, nullptr, CDIM, 0);
    }
}